// round 5
// baseline (speedup 1.0000x reference)
#include <cuda_runtime.h>

// Polar decomposition of A = rotation[n] @ mat. 4 matrices/thread as two
// independent f32x2-packed chains (ILP=2), smem-staged coalesced I/O.
// Head: det-scaled Newton  X <- 0.5*g*X + 0.5*g^2*sign(det)*cof(X), g=|det|^(-1/3)
// Tail: Newton-Schulz X <- X(3I - X^T X)/2 (pure FMA2), guarded by tr < 4.5.

#define TPB 128
#define MPT 4
typedef unsigned long long u64;

__device__ __forceinline__ u64 f2pack(float lo, float hi) {
    u64 r; asm("mov.b64 %0, {%1, %2};" : "=l"(r) : "f"(lo), "f"(hi)); return r;
}
__device__ __forceinline__ void f2unpack(u64 v, float& lo, float& hi) {
    asm("mov.b64 {%0, %1}, %2;" : "=f"(lo), "=f"(hi) : "l"(v));
}
__device__ __forceinline__ u64 f2mul(u64 a, u64 b) {
    u64 d; asm("mul.rn.f32x2 %0, %1, %2;" : "=l"(d) : "l"(a), "l"(b)); return d;
}
__device__ __forceinline__ u64 f2add(u64 a, u64 b) {
    u64 d; asm("add.rn.f32x2 %0, %1, %2;" : "=l"(d) : "l"(a), "l"(b)); return d;
}
__device__ __forceinline__ u64 f2fma(u64 a, u64 b, u64 c) {
    u64 d; asm("fma.rn.f32x2 %0, %1, %2, %3;" : "=l"(d) : "l"(a), "l"(b), "l"(c)); return d;
}
__device__ __forceinline__ u64 f2neg(u64 a) { return a ^ 0x8000000080000000ULL; }
__device__ __forceinline__ u64 f2msub(u64 a, u64 b, u64 c, u64 d) {
    return f2fma(a, b, f2neg(f2mul(c, d)));
}
__device__ __forceinline__ float lg2_fast(float x) {
    float r; asm("lg2.approx.f32 %0, %1;" : "=f"(r) : "f"(x)); return r;
}
__device__ __forceinline__ float ex2_fast(float x) {
    float r; asm("ex2.approx.f32 %0, %1;" : "=f"(r) : "f"(x)); return r;
}

struct P2 { u64 x0,x1,x2,x3,x4,x5,x6,x7,x8; };

__device__ __forceinline__ void newton_step(P2& X) {
    const u64 c00 = f2msub(X.x4, X.x8, X.x5, X.x7);
    const u64 c01 = f2msub(X.x5, X.x6, X.x3, X.x8);
    const u64 c02 = f2msub(X.x3, X.x7, X.x4, X.x6);
    const u64 c10 = f2msub(X.x2, X.x7, X.x1, X.x8);
    const u64 c11 = f2msub(X.x0, X.x8, X.x2, X.x6);
    const u64 c12 = f2msub(X.x1, X.x6, X.x0, X.x7);
    const u64 c20 = f2msub(X.x1, X.x5, X.x2, X.x4);
    const u64 c21 = f2msub(X.x2, X.x3, X.x0, X.x5);
    const u64 c22 = f2msub(X.x0, X.x4, X.x1, X.x3);
    const u64 det = f2fma(X.x0, c00, f2fma(X.x1, c01, f2mul(X.x2, c02)));

    float dl, dh;
    f2unpack(det, dl, dh);
    const float gl = ex2_fast(-0.33333333f * lg2_fast(fmaxf(fabsf(dl), 1e-36f)));
    const float gh = ex2_fast(-0.33333333f * lg2_fast(fmaxf(fabsf(dh), 1e-36f)));
    const float rl = copysignf(0.5f * gl * gl, dl);   // 0.5/(g*det) == 0.5*g^2*sign(det)
    const float rh = copysignf(0.5f * gh * gh, dh);
    const u64 hg = f2pack(0.5f * gl, 0.5f * gh);
    const u64 rr = f2pack(rl, rh);

    X.x0 = f2fma(rr, c00, f2mul(hg, X.x0));
    X.x1 = f2fma(rr, c01, f2mul(hg, X.x1));
    X.x2 = f2fma(rr, c02, f2mul(hg, X.x2));
    X.x3 = f2fma(rr, c10, f2mul(hg, X.x3));
    X.x4 = f2fma(rr, c11, f2mul(hg, X.x4));
    X.x5 = f2fma(rr, c12, f2mul(hg, X.x5));
    X.x6 = f2fma(rr, c20, f2mul(hg, X.x6));
    X.x7 = f2fma(rr, c21, f2mul(hg, X.x7));
    X.x8 = f2fma(rr, c22, f2mul(hg, X.x8));
}

__device__ __forceinline__ void gram(const P2& X, u64 B[6], u64& tr) {
    B[0] = f2fma(X.x0, X.x0, f2fma(X.x3, X.x3, f2mul(X.x6, X.x6)));
    B[1] = f2fma(X.x0, X.x1, f2fma(X.x3, X.x4, f2mul(X.x6, X.x7)));
    B[2] = f2fma(X.x0, X.x2, f2fma(X.x3, X.x5, f2mul(X.x6, X.x8)));
    B[3] = f2fma(X.x1, X.x1, f2fma(X.x4, X.x4, f2mul(X.x7, X.x7)));
    B[4] = f2fma(X.x1, X.x2, f2fma(X.x4, X.x5, f2mul(X.x7, X.x8)));
    B[5] = f2fma(X.x2, X.x2, f2fma(X.x5, X.x5, f2mul(X.x8, X.x8)));
    tr = f2add(B[0], f2add(B[3], B[5]));
}

__device__ __forceinline__ void ns_update(P2& X, const u64 B[6]) {
    const u64 c15  = f2pack(1.5f, 1.5f);
    const u64 cm05 = f2pack(-0.5f, -0.5f);
    const u64 p00 = f2fma(B[0], cm05, c15);
    const u64 p01 = f2mul(B[1], cm05);
    const u64 p02 = f2mul(B[2], cm05);
    const u64 p11 = f2fma(B[3], cm05, c15);
    const u64 p12 = f2mul(B[4], cm05);
    const u64 p22 = f2fma(B[5], cm05, c15);

    const u64 y0 = f2fma(X.x0, p00, f2fma(X.x1, p01, f2mul(X.x2, p02)));
    const u64 y1 = f2fma(X.x0, p01, f2fma(X.x1, p11, f2mul(X.x2, p12)));
    const u64 y2 = f2fma(X.x0, p02, f2fma(X.x1, p12, f2mul(X.x2, p22)));
    const u64 y3 = f2fma(X.x3, p00, f2fma(X.x4, p01, f2mul(X.x5, p02)));
    const u64 y4 = f2fma(X.x3, p01, f2fma(X.x4, p11, f2mul(X.x5, p12)));
    const u64 y5 = f2fma(X.x3, p02, f2fma(X.x4, p12, f2mul(X.x5, p22)));
    const u64 y6 = f2fma(X.x6, p00, f2fma(X.x7, p01, f2mul(X.x8, p02)));
    const u64 y7 = f2fma(X.x6, p01, f2fma(X.x7, p11, f2mul(X.x8, p12)));
    const u64 y8 = f2fma(X.x6, p02, f2fma(X.x7, p12, f2mul(X.x8, p22)));
    X.x0 = y0; X.x1 = y1; X.x2 = y2;
    X.x3 = y3; X.x4 = y4; X.x5 = y5;
    X.x6 = y6; X.x7 = y7; X.x8 = y8;
}

__device__ __forceinline__ P2 mul_rm(const u64 R[9], const u64 M[9]) {
    P2 X;
    X.x0 = f2fma(R[0], M[0], f2fma(R[1], M[3], f2mul(R[2], M[6])));
    X.x1 = f2fma(R[0], M[1], f2fma(R[1], M[4], f2mul(R[2], M[7])));
    X.x2 = f2fma(R[0], M[2], f2fma(R[1], M[5], f2mul(R[2], M[8])));
    X.x3 = f2fma(R[3], M[0], f2fma(R[4], M[3], f2mul(R[5], M[6])));
    X.x4 = f2fma(R[3], M[1], f2fma(R[4], M[4], f2mul(R[5], M[7])));
    X.x5 = f2fma(R[3], M[2], f2fma(R[4], M[5], f2mul(R[5], M[8])));
    X.x6 = f2fma(R[6], M[0], f2fma(R[7], M[3], f2mul(R[8], M[6])));
    X.x7 = f2fma(R[6], M[1], f2fma(R[7], M[4], f2mul(R[8], M[7])));
    X.x8 = f2fma(R[6], M[2], f2fma(R[7], M[5], f2mul(R[8], M[8])));
    return X;
}

__global__ void __launch_bounds__(TPB)
polar4s_kernel(const float* __restrict__ rot,
               const float* __restrict__ mat,
               float* __restrict__ out,
               float* __restrict__ logdet,
               int N)
{
    __shared__ float s[TPB * MPT * 9];                 // 18 KB
    const int tid  = threadIdx.x;
    const int base = blockIdx.x * (TPB * MPT);
    const int nmat = min(TPB * MPT, N - base);
    const int nflt = nmat * 9;

    // ---- cooperative coalesced load: global -> smem ----
    {
        const float* g = rot + (size_t)base * 9;
        const int nv = nflt >> 2;
        const float4* g4 = reinterpret_cast<const float4*>(g);
        float4* s4 = reinterpret_cast<float4*>(s);
        for (int i = tid; i < nv; i += TPB) s4[i] = g4[i];
        for (int i = (nv << 2) + tid; i < nflt; i += TPB) s[i] = g[i];
    }

    u64 M[9];
    #pragma unroll
    for (int k = 0; k < 9; ++k) { const float m = __ldg(mat + k); M[k] = f2pack(m, m); }
    __syncthreads();

    // gather this thread's 4 matrices from smem (identity for tail slots)
    const int lo = tid * (MPT * 9);
    const int g0 = base + tid * MPT;
    u64 RA[9], RB[9];
    #pragma unroll
    for (int k = 0; k < 9; ++k) {
        const float idv = (k == 0 || k == 4 || k == 8) ? 1.0f : 0.0f;
        const float a0 = (g0     < N) ? s[lo +      k] : idv;
        const float a1 = (g0 + 1 < N) ? s[lo +  9 + k] : idv;
        const float a2 = (g0 + 2 < N) ? s[lo + 18 + k] : idv;
        const float a3 = (g0 + 3 < N) ? s[lo + 27 + k] : idv;
        RA[k] = f2pack(a0, a1);
        RB[k] = f2pack(a2, a3);
    }
    __syncthreads();                                    // smem reused for store

    P2 XA = mul_rm(RA, M);
    P2 XB = mul_rm(RB, M);

    // ---- head: 3 det-scaled steps, no checks ----
    #pragma unroll
    for (int it = 0; it < 3; ++it) { newton_step(XA); newton_step(XB); }

    // ---- adaptive tail: NS when safe, else another scaled step ----
    #pragma unroll 1
    for (int it = 0; it < 8; ++it) {
        u64 BA[6], BB[6], trA, trB;
        gram(XA, BA, trA);
        gram(XB, BB, trB);
        float ta0, ta1, tb0, tb1;
        f2unpack(trA, ta0, ta1);
        f2unpack(trB, tb0, tb1);
        const float err = fmaxf(fmaxf(fabsf(ta0 - 3.0f), fabsf(ta1 - 3.0f)),
                                fmaxf(fabsf(tb0 - 3.0f), fabsf(tb1 - 3.0f)));
        if (__all_sync(0xffffffffu, err < 3e-4f)) break;
        const float mx = fmaxf(fmaxf(ta0, ta1), fmaxf(tb0, tb1));
        if (__all_sync(0xffffffffu, mx < 4.5f)) {
            ns_update(XA, BA);
            ns_update(XB, BB);
        } else {
            newton_step(XA);
            newton_step(XB);
        }
    }

    // ---- scatter to smem, cooperative coalesced store ----
    {
        float a, b;
        f2unpack(XA.x0, a, b); s[lo + 0] = a; s[lo +  9] = b;
        f2unpack(XA.x1, a, b); s[lo + 1] = a; s[lo + 10] = b;
        f2unpack(XA.x2, a, b); s[lo + 2] = a; s[lo + 11] = b;
        f2unpack(XA.x3, a, b); s[lo + 3] = a; s[lo + 12] = b;
        f2unpack(XA.x4, a, b); s[lo + 4] = a; s[lo + 13] = b;
        f2unpack(XA.x5, a, b); s[lo + 5] = a; s[lo + 14] = b;
        f2unpack(XA.x6, a, b); s[lo + 6] = a; s[lo + 15] = b;
        f2unpack(XA.x7, a, b); s[lo + 7] = a; s[lo + 16] = b;
        f2unpack(XA.x8, a, b); s[lo + 8] = a; s[lo + 17] = b;
        f2unpack(XB.x0, a, b); s[lo + 18] = a; s[lo + 27] = b;
        f2unpack(XB.x1, a, b); s[lo + 19] = a; s[lo + 28] = b;
        f2unpack(XB.x2, a, b); s[lo + 20] = a; s[lo + 29] = b;
        f2unpack(XB.x3, a, b); s[lo + 21] = a; s[lo + 30] = b;
        f2unpack(XB.x4, a, b); s[lo + 22] = a; s[lo + 31] = b;
        f2unpack(XB.x5, a, b); s[lo + 23] = a; s[lo + 32] = b;
        f2unpack(XB.x6, a, b); s[lo + 24] = a; s[lo + 33] = b;
        f2unpack(XB.x7, a, b); s[lo + 25] = a; s[lo + 34] = b;
        f2unpack(XB.x8, a, b); s[lo + 26] = a; s[lo + 35] = b;
    }
    __syncthreads();
    {
        float* g = out + (size_t)base * 9;
        const int nv = nflt >> 2;
        const float4* s4 = reinterpret_cast<const float4*>(s);
        float4* g4 = reinterpret_cast<float4*>(g);
        for (int i = tid; i < nv; i += TPB) g4[i] = s4[i];
        for (int i = (nv << 2) + tid; i < nflt; i += TPB) g[i] = s[i];
    }

    for (int i = tid; i < nmat; i += TPB) logdet[base + i] = 0.0f;
}

__global__ void zero_tail_kernel(float* __restrict__ p, long long n)
{
    long long i = (long long)blockIdx.x * blockDim.x + threadIdx.x;
    if (i < n) p[i] = 0.0f;
}

extern "C" void kernel_launch(void* const* d_in, const int* in_sizes, int n_in,
                              void* d_out, int out_size)
{
    const float* rot = (const float*)d_in[0];
    const float* mat = (const float*)d_in[1];
    float* out = (float*)d_out;

    const int N = in_sizes[0] / 9;
    float* logdet = out + (size_t)N * 9;

    const int mats_per_block = TPB * MPT;
    const int blocks = (N + mats_per_block - 1) / mats_per_block;
    polar4s_kernel<<<blocks, TPB>>>(rot, mat, out, logdet, N);

    const long long used = 10LL * N;
    if ((long long)out_size > used) {
        const long long extra = (long long)out_size - used;
        const int zb = (int)((extra + 255) / 256);
        zero_tail_kernel<<<zb, 256>>>(out + used, extra);
    }
}